// round 1
// baseline (speedup 1.0000x reference)
#include <cuda_runtime.h>
#include <cuda_bf16.h>

// Sparse 3D conv as gather -> per-offset GEMM -> accumulate.
//   out[n, c] = sum_k mask[k,n] ? features[nmap[k,n], :] @ W[k, :, c] : 0
// Shapes: features [N, 32] f32, nmap/mask [K, N] i32, W [K, 32, 64] f32,
// out [N, 64] f32.  N = 200000, K = 27.
//
// Strategy (round 1, SIMT fp32):
//  - block = 128 output rows x 64 cols, 128 threads, 8x8 register microtile
//  - per k: stage gathered+masked A tile transposed in smem (As[32][128]),
//    weights in smem (Bs[32][64]); dense 128x64x32 GEMM from smem.
//  - A gather is L2-resident (features = 25.6 MB < 126 MB L2).
// FMA-pipe-bound by design; tensor-core (tf32) path is the next step.

#define CIN   32
#define COUT  64
#define TROWS 128      // rows per block
#define NTHREADS 128

__global__ __launch_bounds__(NTHREADS, 4)
void spconv_simt_kernel(const float* __restrict__ features,
                        const int*   __restrict__ nmap,
                        const int*   __restrict__ nmask,
                        const float* __restrict__ weights,
                        float*       __restrict__ out,
                        int n, int kvol)
{
    __shared__ float As[CIN * TROWS];   // transposed: As[i][row], 16 KB
    __shared__ float Bs[CIN * COUT];    // Bs[i][c], 8 KB

    const int tid = threadIdx.x;
    const int R   = blockIdx.x * TROWS;     // first output row of this block
    const int row = R + tid;                // gather row owned by this thread

    // microtile coords: 16 row-groups x 8 col-groups
    const int rg = tid >> 3;                // 0..15
    const int cg = tid & 7;                 // 0..7
    const int r0 = rg * 8;
    const int c0 = cg * 8;

    float acc[8][8];
#pragma unroll
    for (int a = 0; a < 8; ++a)
#pragma unroll
        for (int b = 0; b < 8; ++b)
            acc[a][b] = 0.0f;

    for (int k = 0; k < kvol; ++k) {
        // ---- gather this thread's row for offset k (masked) ----
        float4 f[8];
        bool active = false;
        if (row < n) {
            const long kofs = (long)k * n + row;
            if (nmask[kofs] != 0) {
                const int src = nmap[kofs];
                const float4* fp =
                    reinterpret_cast<const float4*>(features + (size_t)src * CIN);
#pragma unroll
                for (int j = 0; j < 8; ++j) f[j] = fp[j];
                active = true;
            }
        }
        if (!active) {
#pragma unroll
            for (int j = 0; j < 8; ++j)
                f[j] = make_float4(0.f, 0.f, 0.f, 0.f);
        }

        __syncthreads();   // previous iteration's compute finished reading smem

        // ---- store A transposed: As[i*TROWS + tid] ----
#pragma unroll
        for (int j = 0; j < 8; ++j) {
            As[(4 * j + 0) * TROWS + tid] = f[j].x;
            As[(4 * j + 1) * TROWS + tid] = f[j].y;
            As[(4 * j + 2) * TROWS + tid] = f[j].z;
            As[(4 * j + 3) * TROWS + tid] = f[j].w;
        }

        // ---- stage weights for this k: 2048 floats = 512 float4 ----
        {
            const float4* w4 =
                reinterpret_cast<const float4*>(weights + (size_t)k * CIN * COUT);
            float4* b4 = reinterpret_cast<float4*>(Bs);
#pragma unroll
            for (int j = 0; j < 4; ++j)
                b4[tid + NTHREADS * j] = w4[tid + NTHREADS * j];
        }

        __syncthreads();

        // ---- 128x64x32 GEMM from smem, 8x8 microtile ----
#pragma unroll
        for (int i = 0; i < CIN; ++i) {
            const float4 a0 = *reinterpret_cast<const float4*>(&As[i * TROWS + r0]);
            const float4 a1 = *reinterpret_cast<const float4*>(&As[i * TROWS + r0 + 4]);
            const float4 b0 = *reinterpret_cast<const float4*>(&Bs[i * COUT + c0]);
            const float4 b1 = *reinterpret_cast<const float4*>(&Bs[i * COUT + c0 + 4]);
            const float av[8] = {a0.x, a0.y, a0.z, a0.w, a1.x, a1.y, a1.z, a1.w};
            const float bv[8] = {b0.x, b0.y, b0.z, b0.w, b1.x, b1.y, b1.z, b1.w};
#pragma unroll
            for (int a = 0; a < 8; ++a)
#pragma unroll
                for (int b = 0; b < 8; ++b)
                    acc[a][b] = fmaf(av[a], bv[b], acc[a][b]);
        }
    }

    // ---- store C tile ----
#pragma unroll
    for (int a = 0; a < 8; ++a) {
        const int r = R + r0 + a;
        if (r < n) {
            float4* o4 = reinterpret_cast<float4*>(out + (size_t)r * COUT + c0);
            o4[0] = make_float4(acc[a][0], acc[a][1], acc[a][2], acc[a][3]);
            o4[1] = make_float4(acc[a][4], acc[a][5], acc[a][6], acc[a][7]);
        }
    }
}

extern "C" void kernel_launch(void* const* d_in, const int* in_sizes, int n_in,
                              void* d_out, int out_size)
{
    const float* features = (const float*)d_in[0];
    const int*   nmap     = (const int*)  d_in[1];
    const int*   nmask    = (const int*)  d_in[2];
    const float* weights  = (const float*)d_in[3];
    float*       out      = (float*)d_out;

    const int n    = in_sizes[0] / CIN;      // 200000
    const int kvol = in_sizes[1] / n;        // 27

    const int grid = (n + TROWS - 1) / TROWS;
    spconv_simt_kernel<<<grid, NTHREADS>>>(features, nmap, nmask, weights,
                                           out, n, kvol);
}